// round 7
// baseline (speedup 1.0000x reference)
#include <cuda_runtime.h>
#include <cuda_bf16.h>
#include <math.h>
#include <stdint.h>

// Problem constants
#define BB 16      // batch
#define TT 64      // seq len
#define VV 50257   // vocab
#define EE 512     // embed
#define HH 1024    // hidden
#define G3H 3072   // 3*H

#define NCTA_SCAN 128   // persistent scan grid (<=148 SMs -> all resident)

// ---------------- scratch (no allocations allowed) ----------------
__device__ float g_x0[BB * 2 * EE];          // 16x1024
__device__ float g_h0a[BB * HH];             // layer0 h0
__device__ float g_h0b[BB * HH];             // layer1 h0
__device__ float g_xdec[TT * BB * 2 * EE];   // 1024x1024
__device__ float g_xp[TT * BB * G3H];        // 1024x3072 (reused for both layers)
__device__ float g_ys0[TT * BB * HH];        // 1024x1024
__device__ float g_ys1[TT * BB * HH];        // 1024x1024
__device__ float g_final[TT * BB * EE];      // 1024x512

// grid-barrier state (self-restoring: count returns to 0; gen compared by equality)
__device__ unsigned g_bar_count = 0;
__device__ unsigned g_bar_gen   = 0;

// ---------------- small builders ----------------
__global__ void build_x0(const float* __restrict__ init, float* __restrict__ x0) {
    int b = blockIdx.x;
    for (int c = threadIdx.x; c < EE; c += blockDim.x) {
        float v = init[b * EE + c];
        x0[b * (2 * EE) + c] = v;
        x0[b * (2 * EE) + EE + c] = v;
    }
}

__global__ void build_xdec(const int* __restrict__ helper,
                           const float* __restrict__ emb,
                           const float* __restrict__ init,
                           float* __restrict__ xdec) {
    int r = blockIdx.x;            // r = t*B + b
    int t = r >> 4;
    int b = r & 15;
    int tok = helper[b * TT + t];
    const float* src0 = emb + (size_t)tok * EE;
    const float* src1 = init + b * EE;
    float* dst = xdec + (size_t)r * (2 * EE);
    for (int c = threadIdx.x; c < EE; c += blockDim.x) {
        dst[c] = src0[c];
        dst[EE + c] = src1[c];
    }
}

// ---------------- tf32 helpers ----------------
__device__ __forceinline__ uint32_t f2tf32(float x) {
    uint32_t r;
    asm("cvt.rna.tf32.f32 %0, %1;" : "=r"(r) : "f"(x));
    return r;
}

__device__ __forceinline__ void mma_tf32(float* c, const uint32_t* a, const uint32_t* b) {
    asm volatile(
        "mma.sync.aligned.m16n8k8.row.col.f32.tf32.tf32.f32 "
        "{%0,%1,%2,%3}, {%4,%5,%6,%7}, {%8,%9}, {%0,%1,%2,%3};"
        : "+f"(c[0]), "+f"(c[1]), "+f"(c[2]), "+f"(c[3])
        : "r"(a[0]), "r"(a[1]), "r"(a[2]), "r"(a[3]), "r"(b[0]), "r"(b[1]));
}

// ---------------- tensor-core GEMM: C = A(MxK) * B(NxK)^T ----------------
// Block tile 128x128, K tile 32. 8 warps: warp (wm,wn) owns 64x32.
// DOUBLE-BUFFERED smem ping-pong: one __syncthreads per K-tile.
// flags: bit0 = add bias[n]; bit1 = tanh; bit2 = (b,t) transposed store (logits)
// COMP: compensated tf32 split (Ah*Bh + Al*Bh + Ah*Bl) ~ fp32 accuracy.

// per-stage float counts
#define STG_FAST 8192    // Ah(4096)+Bh(4096)
#define STG_COMP 16384   // + Al(4096)+Bl(4096)

template<bool COMP>
__device__ __forceinline__ void store_stage(
    float* stage, const float4* pa, const float4* pb, int lrow, int lk4) {
    float* Ah = stage;
    float* Bh = stage + 4096;
    float* Al = COMP ? (stage + 8192)  : nullptr;
    float* Bl = COMP ? (stage + 12288) : nullptr;
#pragma unroll
    for (int p = 0; p < 4; p++) {
        int m = lrow + p * 32;
        const float* av = (const float*)&pa[p];
        const float* bv = (const float*)&pb[p];
#pragma unroll
        for (int i = 0; i < 4; i++) {
            int k = lk4 + i;
            int ks = k >> 3, kc = k & 7;
            {
                int mt = m >> 4, r = m & 15;
                int ln = ((r & 7) << 2) | (kc & 3);
                int slot = (r >> 3) | ((kc >> 2) << 1);
                int idx = (((ks * 8 + mt) * 32 + ln) << 2) | slot;
                float x = av[i];
                uint32_t hb = f2tf32(x);
                Ah[idx] = __uint_as_float(hb);
                if (COMP) Al[idx] = __uint_as_float(f2tf32(x - __uint_as_float(hb)));
            }
            {
                int nt = m >> 3;
                int ln = ((m & 7) << 2) | (kc & 3);
                int slot = kc >> 2;
                int idx = (((ks * 16 + nt) * 32 + ln) << 1) | slot;
                float x = bv[i];
                uint32_t hb = f2tf32(x);
                Bh[idx] = __uint_as_float(hb);
                if (COMP) Bl[idx] = __uint_as_float(f2tf32(x - __uint_as_float(hb)));
            }
        }
    }
}

template<bool COMP>
__global__ void __launch_bounds__(256)
gemm_tf32(const float* __restrict__ A, const float* __restrict__ B,
          float* __restrict__ C, int M, int N, int K,
          const float* __restrict__ bias, int flags) {
    extern __shared__ float smem[];
    const int STG = COMP ? STG_COMP : STG_FAST;

    const int tid  = threadIdx.x;
    const int lane = tid & 31;
    const int warp = tid >> 5;
    const int wm = warp >> 2;     // 0..1
    const int wn = warp & 3;      // 0..3
    const int m0 = blockIdx.y * 128;
    const int n0 = blockIdx.x * 128;

    float acc[4][4][4];
#pragma unroll
    for (int i = 0; i < 4; i++)
#pragma unroll
        for (int j = 0; j < 4; j++)
#pragma unroll
            for (int s = 0; s < 4; s++) acc[i][j][s] = 0.0f;

    const int lrow = tid >> 3;        // 0..31
    const int lk4  = (tid & 7) * 4;   // 0,4,...,28
    const int nK = K >> 5;

    float4 pa[4], pb[4];

    // ---- load + store K-tile 0 into stage 0 ----
#pragma unroll
    for (int p = 0; p < 4; p++) {
        int gr = m0 + lrow + p * 32;
        pa[p] = (gr < M) ? *(const float4*)&A[(size_t)gr * K + lk4]
                         : make_float4(0.f, 0.f, 0.f, 0.f);
        int gn = n0 + lrow + p * 32;
        pb[p] = (gn < N) ? *(const float4*)&B[(size_t)gn * K + lk4]
                         : make_float4(0.f, 0.f, 0.f, 0.f);
    }
    store_stage<COMP>(smem, pa, pb, lrow, lk4);
    __syncthreads();

    for (int kt = 0; kt < nK; kt++) {
        const bool more = (kt + 1 < nK);
        float* cur = smem + (kt & 1) * STG;
        float* nxt = smem + ((kt + 1) & 1) * STG;

        // ---- prefetch next K-tile (global -> regs) ----
        if (more) {
            int kbase = (kt + 1) * 32 + lk4;
#pragma unroll
            for (int p = 0; p < 4; p++) {
                int gr = m0 + lrow + p * 32;
                pa[p] = (gr < M) ? *(const float4*)&A[(size_t)gr * K + kbase]
                                 : make_float4(0.f, 0.f, 0.f, 0.f);
                int gn = n0 + lrow + p * 32;
                pb[p] = (gn < N) ? *(const float4*)&B[(size_t)gn * K + kbase]
                                 : make_float4(0.f, 0.f, 0.f, 0.f);
            }
        }

        // ---- compute 4 k-steps from current stage ----
        float* Ah = cur;
        float* Bh = cur + 4096;
        float* Al = COMP ? (cur + 8192)  : nullptr;
        float* Bl = COMP ? (cur + 12288) : nullptr;
#pragma unroll
        for (int ks = 0; ks < 4; ks++) {
            uint32_t af[4][4], bf[4][2];
            uint32_t al[4][4], bl[4][2];
#pragma unroll
            for (int mt = 0; mt < 4; mt++) {
                const float4 v = *(const float4*)(Ah + (((ks * 8 + (wm * 4 + mt)) * 32 + lane) << 2));
                af[mt][0] = __float_as_uint(v.x); af[mt][1] = __float_as_uint(v.y);
                af[mt][2] = __float_as_uint(v.z); af[mt][3] = __float_as_uint(v.w);
                if (COMP) {
                    const float4 w = *(const float4*)(Al + (((ks * 8 + (wm * 4 + mt)) * 32 + lane) << 2));
                    al[mt][0] = __float_as_uint(w.x); al[mt][1] = __float_as_uint(w.y);
                    al[mt][2] = __float_as_uint(w.z); al[mt][3] = __float_as_uint(w.w);
                }
            }
#pragma unroll
            for (int nt = 0; nt < 4; nt++) {
                const float2 v = *(const float2*)(Bh + (((ks * 16 + (wn * 4 + nt)) * 32 + lane) << 1));
                bf[nt][0] = __float_as_uint(v.x); bf[nt][1] = __float_as_uint(v.y);
                if (COMP) {
                    const float2 w = *(const float2*)(Bl + (((ks * 16 + (wn * 4 + nt)) * 32 + lane) << 1));
                    bl[nt][0] = __float_as_uint(w.x); bl[nt][1] = __float_as_uint(w.y);
                }
            }
#pragma unroll
            for (int mt = 0; mt < 4; mt++)
#pragma unroll
                for (int nt = 0; nt < 4; nt++) {
                    mma_tf32(acc[mt][nt], af[mt], bf[nt]);
                    if (COMP) {
                        mma_tf32(acc[mt][nt], al[mt], bf[nt]);
                        mma_tf32(acc[mt][nt], af[mt], bl[nt]);
                    }
                }
        }

        // ---- store next tile into the other stage; single sync ----
        if (more) {
            store_stage<COMP>(nxt, pa, pb, lrow, lk4);
            __syncthreads();
        }
    }

    // ---- epilogue ----
    const int row = lane >> 2;          // 0..7
    const int col = (lane & 3) * 2;     // 0,2,4,6
#pragma unroll
    for (int mt = 0; mt < 4; mt++) {
#pragma unroll
        for (int nt = 0; nt < 4; nt++) {
#pragma unroll
            for (int s = 0; s < 4; s++) {
                int gm = m0 + wm * 64 + mt * 16 + row + ((s >> 1) ? 8 : 0);
                int gn = n0 + wn * 32 + nt * 8 + col + (s & 1);
                if (gm >= M || gn >= N) continue;
                float v = acc[mt][nt][s];
                if (flags & 1) v += bias[gn];
                if (flags & 2) v = tanhf(v);
                size_t idx;
                if (flags & 4) {
                    int b = gm & 15;     // gm = t*16 + b
                    int t = gm >> 4;
                    idx = (size_t)(b * TT + t) * (size_t)N + (size_t)gn;
                } else {
                    idx = (size_t)gm * (size_t)N + (size_t)gn;
                }
                C[idx] = v;
            }
        }
    }
}

// ---------------- fused h0 kernel (zero initial state) ----------------
__global__ __launch_bounds__(256)
void gru_h0(const float* __restrict__ Wih, const float* __restrict__ bih,
            const float* __restrict__ bhh,
            const float* __restrict__ x,      // BB x HH
            float* __restrict__ hout) {       // BB x HH
    const int warp = threadIdx.x >> 5;
    const int lane = threadIdx.x & 31;
    const int j = blockIdx.x * 8 + warp;

    float accr[BB], accz[BB], accn[BB];
#pragma unroll
    for (int b = 0; b < BB; b++) { accr[b] = 0.f; accz[b] = 0.f; accn[b] = 0.f; }

    const float4* wr = (const float4*)(Wih + (size_t)j * HH);
    const float4* wz = (const float4*)(Wih + (size_t)(HH + j) * HH);
    const float4* wn = (const float4*)(Wih + (size_t)(2 * HH + j) * HH);
    const float4* x4 = (const float4*)x;

#pragma unroll
    for (int it = 0; it < 8; it++) {
        int k4 = it * 32 + lane;
        float4 a = wr[k4];
        float4 bq = wz[k4];
        float4 c = wn[k4];
#pragma unroll
        for (int b = 0; b < BB; b++) {
            float4 hv = x4[b * 256 + k4];
            accr[b] = fmaf(a.x, hv.x, fmaf(a.y, hv.y, fmaf(a.z, hv.z, fmaf(a.w, hv.w, accr[b]))));
            accz[b] = fmaf(bq.x, hv.x, fmaf(bq.y, hv.y, fmaf(bq.z, hv.z, fmaf(bq.w, hv.w, accz[b]))));
            accn[b] = fmaf(c.x, hv.x, fmaf(c.y, hv.y, fmaf(c.z, hv.z, fmaf(c.w, hv.w, accn[b]))));
        }
    }

    float sr = 0.f, sz = 0.f, sn = 0.f;
#pragma unroll
    for (int b = 0; b < BB; b++) {
        float r = accr[b], z = accz[b], n = accn[b];
#pragma unroll
        for (int off = 16; off > 0; off >>= 1) {
            r += __shfl_xor_sync(0xFFFFFFFFu, r, off);
            z += __shfl_xor_sync(0xFFFFFFFFu, z, off);
            n += __shfl_xor_sync(0xFFFFFFFFu, n, off);
        }
        if (lane == b) { sr = r; sz = z; sn = n; }
    }

    if (lane < BB) {
        float xr = sr + bih[j];
        float xz = sz + bih[HH + j];
        float xn = sn + bih[2 * HH + j];
        float r = 1.f / (1.f + expf(-(xr + bhh[j])));
        float z = 1.f / (1.f + expf(-(xz + bhh[HH + j])));
        float n = tanhf(xn + r * bhh[2 * HH + j]);
        hout[lane * HH + j] = (1.f - z) * n;
    }
}

// ---------------- persistent GRU scan (one layer, all 64 steps) ----------------
__device__ __forceinline__ void grid_barrier() {
    __syncthreads();
    if (threadIdx.x == 0) {
        __threadfence();
        unsigned gen = atomicAdd(&g_bar_gen, 0u);     // read gen BEFORE arriving
        unsigned arrived = atomicAdd(&g_bar_count, 1u);
        if (arrived == NCTA_SCAN - 1) {
            g_bar_count = 0;
            __threadfence();
            atomicAdd(&g_bar_gen, 1u);
        } else {
            while (atomicAdd(&g_bar_gen, 0u) == gen) { __nanosleep(32); }
        }
    }
    __syncthreads();
}

__global__ void __launch_bounds__(256)
gru_scan(const float* __restrict__ Whh, const float* __restrict__ bhh,
         const float* __restrict__ xp,    // TT x BB x 3H (includes b_ih)
         const float* __restrict__ h0,    // BB x HH
         float* __restrict__ ys) {        // TT x BB x HH
    extern __shared__ float hs[];         // BB*HH floats = 64 KB
    const int tid  = threadIdx.x;
    const int warp = tid >> 5;
    const int lane = tid & 31;
    const int j = blockIdx.x * 8 + warp;  // hidden unit

    const float4* wr = (const float4*)(Whh + (size_t)j * HH);
    const float4* wz = (const float4*)(Whh + (size_t)(HH + j) * HH);
    const float4* wn = (const float4*)(Whh + (size_t)(2 * HH + j) * HH);
    float4 wcr[8], wcz[8], wcn[8];
#pragma unroll
    for (int it = 0; it < 8; it++) {
        int k4 = it * 32 + lane;
        wcr[it] = wr[k4];
        wcz[it] = wz[k4];
        wcn[it] = wn[k4];
    }
    const float bhr = bhh[j];
    const float bhz = bhh[HH + j];
    const float bhn = bhh[2 * HH + j];

    for (int t = 0; t < TT; t++) {
        const float4* hp4 = (const float4*)((t == 0) ? h0 : (ys + (size_t)(t - 1) * BB * HH));
#pragma unroll 4
        for (int idx = tid; idx < BB * HH / 4; idx += 256)
            ((float4*)hs)[idx] = hp4[idx];
        __syncthreads();

        float accr[BB], accz[BB], accn[BB];
#pragma unroll
        for (int b = 0; b < BB; b++) { accr[b] = 0.f; accz[b] = 0.f; accn[b] = 0.f; }

        const float4* h4 = (const float4*)hs;
#pragma unroll
        for (int it = 0; it < 8; it++) {
            int k4 = it * 32 + lane;
            float4 a = wcr[it], bq = wcz[it], c = wcn[it];
#pragma unroll
            for (int b = 0; b < BB; b++) {
                float4 hv = h4[b * 256 + k4];
                accr[b] = fmaf(a.x, hv.x, fmaf(a.y, hv.y, fmaf(a.z, hv.z, fmaf(a.w, hv.w, accr[b]))));
                accz[b] = fmaf(bq.x, hv.x, fmaf(bq.y, hv.y, fmaf(bq.z, hv.z, fmaf(bq.w, hv.w, accz[b]))));
                accn[b] = fmaf(c.x, hv.x, fmaf(c.y, hv.y, fmaf(c.z, hv.z, fmaf(c.w, hv.w, accn[b]))));
            }
        }

        float sr = 0.f, sz = 0.f, sn = 0.f;
#pragma unroll
        for (int b = 0; b < BB; b++) {
            float r = accr[b], z = accz[b], n = accn[b];
#pragma unroll
            for (int off = 16; off > 0; off >>= 1) {
                r += __shfl_xor_sync(0xFFFFFFFFu, r, off);
                z += __shfl_xor_sync(0xFFFFFFFFu, z, off);
                n += __shfl_xor_sync(0xFFFFFFFFu, n, off);
            }
            if (lane == b) { sr = r; sz = z; sn = n; }
        }

        if (lane < BB) {
            int b = lane;
            const float* xg = xp + (size_t)t * BB * G3H + (size_t)b * G3H;
            float xr = xg[j];
            float xz = xg[HH + j];
            float xn = xg[2 * HH + j];
            float hp = hs[b * HH + j];
            float r = 1.f / (1.f + expf(-(xr + sr + bhr)));
            float z = 1.f / (1.f + expf(-(xz + sz + bhz)));
            float n = tanhf(xn + r * (sn + bhn));
            ys[(size_t)t * BB * HH + b * HH + j] = (1.f - z) * n + z * hp;
        }

        grid_barrier();   // all writes of step t visible before step t+1 staging
    }
}

// ---------------- host orchestration ----------------
#define SMEM_COMP  (2 * STG_COMP * 4)   // 128 KB
#define SMEM_FAST  (2 * STG_FAST * 4)   // 64 KB
#define SMEM_SCAN  (BB * HH * 4)        // 64 KB

extern "C" void kernel_launch(void* const* d_in, const int* in_sizes, int n_in,
                              void* d_out, int out_size) {
    const float* init  = (const float*)d_in[0];
    const int*   helper= (const int*)  d_in[1];
    const float* emb   = (const float*)d_in[2];
    const float* W_ih0 = (const float*)d_in[3];
    const float* W_hh0 = (const float*)d_in[4];
    const float* b_ih0 = (const float*)d_in[5];
    const float* b_hh0 = (const float*)d_in[6];
    const float* W_ih1 = (const float*)d_in[7];
    const float* W_hh1 = (const float*)d_in[8];
    const float* b_ih1 = (const float*)d_in[9];
    const float* b_hh1 = (const float*)d_in[10];
    const float* Wc_w  = (const float*)d_in[11];
    const float* Wc_b  = (const float*)d_in[12];
    float* out = (float*)d_out;

    float *x0, *h0a, *h0b, *xdec, *xp, *ys0, *ys1, *fin;
    cudaGetSymbolAddress((void**)&x0,   g_x0);
    cudaGetSymbolAddress((void**)&h0a,  g_h0a);
    cudaGetSymbolAddress((void**)&h0b,  g_h0b);
    cudaGetSymbolAddress((void**)&xdec, g_xdec);
    cudaGetSymbolAddress((void**)&xp,   g_xp);
    cudaGetSymbolAddress((void**)&ys0,  g_ys0);
    cudaGetSymbolAddress((void**)&ys1,  g_ys1);
    cudaGetSymbolAddress((void**)&fin,  g_final);

    cudaFuncSetAttribute(gemm_tf32<true>,  cudaFuncAttributeMaxDynamicSharedMemorySize, SMEM_COMP);
    cudaFuncSetAttribute(gemm_tf32<false>, cudaFuncAttributeMaxDynamicSharedMemorySize, SMEM_FAST);
    cudaFuncSetAttribute(gru_scan,         cudaFuncAttributeMaxDynamicSharedMemorySize, SMEM_SCAN);

    dim3 blk(256);

    // ---- h0 (fused small path) ----
    build_x0<<<BB, blk>>>(init, x0);
    gru_h0<<<128, blk>>>(W_ih0, b_ih0, b_hh0, x0, h0a);
    gru_h0<<<128, blk>>>(W_ih1, b_ih1, b_hh1, h0a, h0b);

    // ---- decoder inputs ----
    build_xdec<<<TT * BB, blk>>>(helper, emb, init, xdec);

    // ---- layer 0: xp (single-pass tf32) then persistent scan ----
    gemm_tf32<false><<<dim3(G3H / 128, TT * BB / 128), blk, SMEM_FAST>>>(
        xdec, W_ih0, xp, TT * BB, G3H, 2 * EE, b_ih0, 1);
    gru_scan<<<NCTA_SCAN, blk, SMEM_SCAN>>>(W_hh0, b_hh0, xp, h0a, ys0);

    // ---- layer 1: xp (single-pass tf32) then persistent scan ----
    gemm_tf32<false><<<dim3(G3H / 128, TT * BB / 128), blk, SMEM_FAST>>>(
        ys0, W_ih1, xp, TT * BB, G3H, HH, b_ih1, 1);
    gru_scan<<<NCTA_SCAN, blk, SMEM_SCAN>>>(W_hh1, b_hh1, xp, h0b, ys1);

    // ---- final = tanh(ys1 @ Wc_w^T + Wc_b), compensated ----
    gemm_tf32<true><<<dim3(EE / 128, TT * BB / 128), blk, SMEM_COMP>>>(
        ys1, Wc_w, fin, TT * BB, EE, HH, Wc_b, 1 | 2);

    // ---- logits = final @ emb^T, single-pass tf32, stored (B,T,V) ----
    gemm_tf32<false><<<dim3((VV + 127) / 128, TT * BB / 128), blk, SMEM_FAST>>>(
        fin, emb, out, TT * BB, VV, EE, nullptr, 4);
}

// round 8
// speedup vs baseline: 1.5554x; 1.5554x over previous
#include <cuda_runtime.h>
#include <cuda_bf16.h>
#include <math.h>
#include <stdint.h>

// Problem constants
#define BB 16      // batch
#define TT 64      // seq len
#define VV 50257   // vocab
#define EE 512     // embed
#define HH 1024    // hidden
#define G3H 3072   // 3*H

#define NCTA_SCAN 128   // persistent scan grid (<=148 SMs -> all resident)

// ---------------- scratch (no allocations allowed) ----------------
__device__ float g_x0[BB * 2 * EE];          // 16x1024
__device__ float g_h0a[BB * HH];             // layer0 h0
__device__ float g_h0b[BB * HH];             // layer1 h0
__device__ float g_xdec[TT * BB * 2 * EE];   // 1024x1024
__device__ float g_xp[TT * BB * G3H];        // 1024x3072 (reused for both layers)
__device__ float g_ys0[TT * BB * HH];        // 1024x1024
__device__ float g_ys1[TT * BB * HH];        // 1024x1024
__device__ float g_final[TT * BB * EE];      // 1024x512

// grid-barrier state (self-restoring: count returns to 0; gen compared by equality)
__device__ unsigned g_bar_count = 0;
__device__ unsigned g_bar_gen   = 0;

// ---------------- small builders ----------------
__global__ void build_x0(const float* __restrict__ init, float* __restrict__ x0) {
    int b = blockIdx.x;
    for (int c = threadIdx.x; c < EE; c += blockDim.x) {
        float v = init[b * EE + c];
        x0[b * (2 * EE) + c] = v;
        x0[b * (2 * EE) + EE + c] = v;
    }
}

__global__ void build_xdec(const int* __restrict__ helper,
                           const float* __restrict__ emb,
                           const float* __restrict__ init,
                           float* __restrict__ xdec) {
    int r = blockIdx.x;            // r = t*B + b
    int t = r >> 4;
    int b = r & 15;
    int tok = helper[b * TT + t];
    const float* src0 = emb + (size_t)tok * EE;
    const float* src1 = init + b * EE;
    float* dst = xdec + (size_t)r * (2 * EE);
    for (int c = threadIdx.x; c < EE; c += blockDim.x) {
        dst[c] = src0[c];
        dst[EE + c] = src1[c];
    }
}

// ---------------- tf32 helpers ----------------
__device__ __forceinline__ uint32_t f2tf32(float x) {
    uint32_t r;
    asm("cvt.rna.tf32.f32 %0, %1;" : "=r"(r) : "f"(x));
    return r;
}

__device__ __forceinline__ void mma_tf32(float* c, const uint32_t* a, const uint32_t* b) {
    asm volatile(
        "mma.sync.aligned.m16n8k8.row.col.f32.tf32.tf32.f32 "
        "{%0,%1,%2,%3}, {%4,%5,%6,%7}, {%8,%9}, {%0,%1,%2,%3};"
        : "+f"(c[0]), "+f"(c[1]), "+f"(c[2]), "+f"(c[3])
        : "r"(a[0]), "r"(a[1]), "r"(a[2]), "r"(a[3]), "r"(b[0]), "r"(b[1]));
}

// ---------------- tensor-core GEMM: C = A(MxK) * B(NxK)^T ----------------
// Block tile 128x128, K tile 32. 8 warps: warp (wm,wn) owns 64x32.
// Single-buffer (round-6 baseline) + ks-XOR bank swizzle on the fragment
// row index: STS conflict degree 4 -> 1 (the ks stride is a multiple of
// 32 banks, so without the XOR the 8-lane lk4 groups collide on 2 banks).
// flags: bit0 = add bias[n]; bit1 = tanh; bit2 = (b,t) transposed store (logits)
// COMP: compensated tf32 split (Ah*Bh + Al*Bh + Ah*Bl) ~ fp32 accuracy.
template<bool COMP>
__global__ void __launch_bounds__(256)
gemm_tf32(const float* __restrict__ A, const float* __restrict__ B,
          float* __restrict__ C, int M, int N, int K,
          const float* __restrict__ bias, int flags) {
    extern __shared__ float smem[];
    float* Ah = smem;             // [ks=4][mt=8][ln=32][slot=4]  4096 floats
    float* Bh = smem + 4096;      // [ks=4][nt=16][ln=32][slot=2] 4096 floats
    float* Al = COMP ? (smem + 8192)  : nullptr;
    float* Bl = COMP ? (smem + 12288) : nullptr;

    const int tid  = threadIdx.x;
    const int lane = tid & 31;
    const int warp = tid >> 5;
    const int wm = warp >> 2;     // 0..1
    const int wn = warp & 3;      // 0..3
    const int m0 = blockIdx.y * 128;
    const int n0 = blockIdx.x * 128;

    float acc[4][4][4];
#pragma unroll
    for (int i = 0; i < 4; i++)
#pragma unroll
        for (int j = 0; j < 4; j++)
#pragma unroll
            for (int s = 0; s < 4; s++) acc[i][j][s] = 0.0f;

    const int lrow = tid >> 3;        // 0..31
    const int lk4  = (tid & 7) * 4;   // 0,4,...,28
    const int nK = K >> 5;

    float4 pa[4], pb[4];

    // ---- prefetch K-tile 0 ----
    {
        int kbase = lk4;
#pragma unroll
        for (int p = 0; p < 4; p++) {
            int gr = m0 + lrow + p * 32;
            pa[p] = (gr < M) ? *(const float4*)&A[(size_t)gr * K + kbase]
                             : make_float4(0.f, 0.f, 0.f, 0.f);
            int gn = n0 + lrow + p * 32;
            pb[p] = (gn < N) ? *(const float4*)&B[(size_t)gn * K + kbase]
                             : make_float4(0.f, 0.f, 0.f, 0.f);
        }
    }
    // store tile 0 into permuted smem (ks-XOR swizzled)
#pragma unroll
    for (int p = 0; p < 4; p++) {
        int m = lrow + p * 32;
        const float* av = (const float*)&pa[p];
        const float* bv = (const float*)&pb[p];
#pragma unroll
        for (int i = 0; i < 4; i++) {
            int k = lk4 + i;
            int ks = k >> 3, kc = k & 7;
            {
                int mt = m >> 4, r = m & 15;
                int ln = (((r & 7) << 2) | (kc & 3)) ^ ks;
                int slot = (r >> 3) | ((kc >> 2) << 1);
                int idx = (((ks * 8 + mt) * 32 + ln) << 2) | slot;
                float x = av[i];
                uint32_t hb = f2tf32(x);
                Ah[idx] = __uint_as_float(hb);
                if (COMP) Al[idx] = __uint_as_float(f2tf32(x - __uint_as_float(hb)));
            }
            {
                int nt = m >> 3;
                int ln = (((m & 7) << 2) | (kc & 3)) ^ ks;
                int slot = kc >> 2;
                int idx = (((ks * 16 + nt) * 32 + ln) << 1) | slot;
                float x = bv[i];
                uint32_t hb = f2tf32(x);
                Bh[idx] = __uint_as_float(hb);
                if (COMP) Bl[idx] = __uint_as_float(f2tf32(x - __uint_as_float(hb)));
            }
        }
    }
    __syncthreads();

    for (int kt = 0; kt < nK; kt++) {
        bool more = (kt + 1 < nK);
        if (more) {
            int kbase = (kt + 1) * 32 + lk4;
#pragma unroll
            for (int p = 0; p < 4; p++) {
                int gr = m0 + lrow + p * 32;
                pa[p] = (gr < M) ? *(const float4*)&A[(size_t)gr * K + kbase]
                                 : make_float4(0.f, 0.f, 0.f, 0.f);
                int gn = n0 + lrow + p * 32;
                pb[p] = (gn < N) ? *(const float4*)&B[(size_t)gn * K + kbase]
                                 : make_float4(0.f, 0.f, 0.f, 0.f);
            }
        }

        // ---- compute 4 k-steps (reads use lane^ks) ----
#pragma unroll
        for (int ks = 0; ks < 4; ks++) {
            const int lsw = lane ^ ks;
            uint32_t af[4][4], bf[4][2];
            uint32_t al[4][4], bl[4][2];
#pragma unroll
            for (int mt = 0; mt < 4; mt++) {
                const float4 v = *(const float4*)(Ah + (((ks * 8 + (wm * 4 + mt)) * 32 + lsw) << 2));
                af[mt][0] = __float_as_uint(v.x); af[mt][1] = __float_as_uint(v.y);
                af[mt][2] = __float_as_uint(v.z); af[mt][3] = __float_as_uint(v.w);
                if (COMP) {
                    const float4 w = *(const float4*)(Al + (((ks * 8 + (wm * 4 + mt)) * 32 + lsw) << 2));
                    al[mt][0] = __float_as_uint(w.x); al[mt][1] = __float_as_uint(w.y);
                    al[mt][2] = __float_as_uint(w.z); al[mt][3] = __float_as_uint(w.w);
                }
            }
#pragma unroll
            for (int nt = 0; nt < 4; nt++) {
                const float2 v = *(const float2*)(Bh + (((ks * 16 + (wn * 4 + nt)) * 32 + lsw) << 1));
                bf[nt][0] = __float_as_uint(v.x); bf[nt][1] = __float_as_uint(v.y);
                if (COMP) {
                    const float2 w = *(const float2*)(Bl + (((ks * 16 + (wn * 4 + nt)) * 32 + lsw) << 1));
                    bl[nt][0] = __float_as_uint(w.x); bl[nt][1] = __float_as_uint(w.y);
                }
            }
#pragma unroll
            for (int mt = 0; mt < 4; mt++)
#pragma unroll
                for (int nt = 0; nt < 4; nt++) {
                    mma_tf32(acc[mt][nt], af[mt], bf[nt]);
                    if (COMP) {
                        mma_tf32(acc[mt][nt], al[mt], bf[nt]);
                        mma_tf32(acc[mt][nt], af[mt], bl[nt]);
                    }
                }
        }
        __syncthreads();

        if (more) {
#pragma unroll
            for (int p = 0; p < 4; p++) {
                int m = lrow + p * 32;
                const float* av = (const float*)&pa[p];
                const float* bv = (const float*)&pb[p];
#pragma unroll
                for (int i = 0; i < 4; i++) {
                    int k = lk4 + i;
                    int ks = k >> 3, kc = k & 7;
                    {
                        int mt = m >> 4, r = m & 15;
                        int ln = (((r & 7) << 2) | (kc & 3)) ^ ks;
                        int slot = (r >> 3) | ((kc >> 2) << 1);
                        int idx = (((ks * 8 + mt) * 32 + ln) << 2) | slot;
                        float x = av[i];
                        uint32_t hb = f2tf32(x);
                        Ah[idx] = __uint_as_float(hb);
                        if (COMP) Al[idx] = __uint_as_float(f2tf32(x - __uint_as_float(hb)));
                    }
                    {
                        int nt = m >> 3;
                        int ln = (((m & 7) << 2) | (kc & 3)) ^ ks;
                        int slot = kc >> 2;
                        int idx = (((ks * 16 + nt) * 32 + ln) << 1) | slot;
                        float x = bv[i];
                        uint32_t hb = f2tf32(x);
                        Bh[idx] = __uint_as_float(hb);
                        if (COMP) Bl[idx] = __uint_as_float(f2tf32(x - __uint_as_float(hb)));
                    }
                }
            }
            __syncthreads();
        }
    }

    // ---- epilogue ----
    const int row = lane >> 2;          // 0..7
    const int col = (lane & 3) * 2;     // 0,2,4,6
#pragma unroll
    for (int mt = 0; mt < 4; mt++) {
#pragma unroll
        for (int nt = 0; nt < 4; nt++) {
#pragma unroll
            for (int s = 0; s < 4; s++) {
                int gm = m0 + wm * 64 + mt * 16 + row + ((s >> 1) ? 8 : 0);
                int gn = n0 + wn * 32 + nt * 8 + col + (s & 1);
                if (gm >= M || gn >= N) continue;
                float v = acc[mt][nt][s];
                if (flags & 1) v += bias[gn];
                if (flags & 2) v = tanhf(v);
                size_t idx;
                if (flags & 4) {
                    int b = gm & 15;     // gm = t*16 + b
                    int t = gm >> 4;
                    idx = (size_t)(b * TT + t) * (size_t)N + (size_t)gn;
                } else {
                    idx = (size_t)gm * (size_t)N + (size_t)gn;
                }
                C[idx] = v;
            }
        }
    }
}

// ---------------- fused h0 kernel (zero initial state) ----------------
__global__ __launch_bounds__(256)
void gru_h0(const float* __restrict__ Wih, const float* __restrict__ bih,
            const float* __restrict__ bhh,
            const float* __restrict__ x,      // BB x HH
            float* __restrict__ hout) {       // BB x HH
    const int warp = threadIdx.x >> 5;
    const int lane = threadIdx.x & 31;
    const int j = blockIdx.x * 8 + warp;

    float accr[BB], accz[BB], accn[BB];
#pragma unroll
    for (int b = 0; b < BB; b++) { accr[b] = 0.f; accz[b] = 0.f; accn[b] = 0.f; }

    const float4* wr = (const float4*)(Wih + (size_t)j * HH);
    const float4* wz = (const float4*)(Wih + (size_t)(HH + j) * HH);
    const float4* wn = (const float4*)(Wih + (size_t)(2 * HH + j) * HH);
    const float4* x4 = (const float4*)x;

#pragma unroll
    for (int it = 0; it < 8; it++) {
        int k4 = it * 32 + lane;
        float4 a = wr[k4];
        float4 bq = wz[k4];
        float4 c = wn[k4];
#pragma unroll
        for (int b = 0; b < BB; b++) {
            float4 hv = x4[b * 256 + k4];
            accr[b] = fmaf(a.x, hv.x, fmaf(a.y, hv.y, fmaf(a.z, hv.z, fmaf(a.w, hv.w, accr[b]))));
            accz[b] = fmaf(bq.x, hv.x, fmaf(bq.y, hv.y, fmaf(bq.z, hv.z, fmaf(bq.w, hv.w, accz[b]))));
            accn[b] = fmaf(c.x, hv.x, fmaf(c.y, hv.y, fmaf(c.z, hv.z, fmaf(c.w, hv.w, accn[b]))));
        }
    }

    float sr = 0.f, sz = 0.f, sn = 0.f;
#pragma unroll
    for (int b = 0; b < BB; b++) {
        float r = accr[b], z = accz[b], n = accn[b];
#pragma unroll
        for (int off = 16; off > 0; off >>= 1) {
            r += __shfl_xor_sync(0xFFFFFFFFu, r, off);
            z += __shfl_xor_sync(0xFFFFFFFFu, z, off);
            n += __shfl_xor_sync(0xFFFFFFFFu, n, off);
        }
        if (lane == b) { sr = r; sz = z; sn = n; }
    }

    if (lane < BB) {
        float xr = sr + bih[j];
        float xz = sz + bih[HH + j];
        float xn = sn + bih[2 * HH + j];
        float r = 1.f / (1.f + expf(-(xr + bhh[j])));
        float z = 1.f / (1.f + expf(-(xz + bhh[HH + j])));
        float n = tanhf(xn + r * bhh[2 * HH + j]);
        hout[lane * HH + j] = (1.f - z) * n;
    }
}

// ---------------- persistent GRU scan (one layer, all 64 steps) ----------------
__device__ __forceinline__ void grid_barrier() {
    __syncthreads();
    if (threadIdx.x == 0) {
        __threadfence();
        unsigned gen = atomicAdd(&g_bar_gen, 0u);     // read gen BEFORE arriving
        unsigned arrived = atomicAdd(&g_bar_count, 1u);
        if (arrived == NCTA_SCAN - 1) {
            g_bar_count = 0;
            __threadfence();
            atomicAdd(&g_bar_gen, 1u);
        } else {
            while (atomicAdd(&g_bar_gen, 0u) == gen) { __nanosleep(32); }
        }
    }
    __syncthreads();
}

__global__ void __launch_bounds__(256)
gru_scan(const float* __restrict__ Whh, const float* __restrict__ bhh,
         const float* __restrict__ xp,    // TT x BB x 3H (includes b_ih)
         const float* __restrict__ h0,    // BB x HH
         float* __restrict__ ys) {        // TT x BB x HH
    extern __shared__ float hs[];         // BB*HH floats = 64 KB
    const int tid  = threadIdx.x;
    const int warp = tid >> 5;
    const int lane = tid & 31;
    const int j = blockIdx.x * 8 + warp;  // hidden unit

    const float4* wr = (const float4*)(Whh + (size_t)j * HH);
    const float4* wz = (const float4*)(Whh + (size_t)(HH + j) * HH);
    const float4* wn = (const float4*)(Whh + (size_t)(2 * HH + j) * HH);
    float4 wcr[8], wcz[8], wcn[8];
#pragma unroll
    for (int it = 0; it < 8; it++) {
        int k4 = it * 32 + lane;
        wcr[it] = wr[k4];
        wcz[it] = wz[k4];
        wcn[it] = wn[k4];
    }
    const float bhr = bhh[j];
    const float bhz = bhh[HH + j];
    const float bhn = bhh[2 * HH + j];

    for (int t = 0; t < TT; t++) {
        const float4* hp4 = (const float4*)((t == 0) ? h0 : (ys + (size_t)(t - 1) * BB * HH));
#pragma unroll 4
        for (int idx = tid; idx < BB * HH / 4; idx += 256)
            ((float4*)hs)[idx] = hp4[idx];
        __syncthreads();

        float accr[BB], accz[BB], accn[BB];
#pragma unroll
        for (int b = 0; b < BB; b++) { accr[b] = 0.f; accz[b] = 0.f; accn[b] = 0.f; }

        const float4* h4 = (const float4*)hs;
#pragma unroll
        for (int it = 0; it < 8; it++) {
            int k4 = it * 32 + lane;
            float4 a = wcr[it], bq = wcz[it], c = wcn[it];
#pragma unroll
            for (int b = 0; b < BB; b++) {
                float4 hv = h4[b * 256 + k4];
                accr[b] = fmaf(a.x, hv.x, fmaf(a.y, hv.y, fmaf(a.z, hv.z, fmaf(a.w, hv.w, accr[b]))));
                accz[b] = fmaf(bq.x, hv.x, fmaf(bq.y, hv.y, fmaf(bq.z, hv.z, fmaf(bq.w, hv.w, accz[b]))));
                accn[b] = fmaf(c.x, hv.x, fmaf(c.y, hv.y, fmaf(c.z, hv.z, fmaf(c.w, hv.w, accn[b]))));
            }
        }

        float sr = 0.f, sz = 0.f, sn = 0.f;
#pragma unroll
        for (int b = 0; b < BB; b++) {
            float r = accr[b], z = accz[b], n = accn[b];
#pragma unroll
            for (int off = 16; off > 0; off >>= 1) {
                r += __shfl_xor_sync(0xFFFFFFFFu, r, off);
                z += __shfl_xor_sync(0xFFFFFFFFu, z, off);
                n += __shfl_xor_sync(0xFFFFFFFFu, n, off);
            }
            if (lane == b) { sr = r; sz = z; sn = n; }
        }

        if (lane < BB) {
            int b = lane;
            const float* xg = xp + (size_t)t * BB * G3H + (size_t)b * G3H;
            float xr = xg[j];
            float xz = xg[HH + j];
            float xn = xg[2 * HH + j];
            float hp = hs[b * HH + j];
            float r = 1.f / (1.f + expf(-(xr + sr + bhr)));
            float z = 1.f / (1.f + expf(-(xz + sz + bhz)));
            float n = tanhf(xn + r * (sn + bhn));
            ys[(size_t)t * BB * HH + b * HH + j] = (1.f - z) * n + z * hp;
        }

        grid_barrier();   // all writes of step t visible before step t+1 staging
    }
}

// ---------------- host orchestration ----------------
#define SMEM_COMP  (16384 * 4)   // 64 KB
#define SMEM_FAST  (16384 * 2)   // 32 KB
#define SMEM_SCAN  (BB * HH * 4) // 64 KB

extern "C" void kernel_launch(void* const* d_in, const int* in_sizes, int n_in,
                              void* d_out, int out_size) {
    const float* init  = (const float*)d_in[0];
    const int*   helper= (const int*)  d_in[1];
    const float* emb   = (const float*)d_in[2];
    const float* W_ih0 = (const float*)d_in[3];
    const float* W_hh0 = (const float*)d_in[4];
    const float* b_ih0 = (const float*)d_in[5];
    const float* b_hh0 = (const float*)d_in[6];
    const float* W_ih1 = (const float*)d_in[7];
    const float* W_hh1 = (const float*)d_in[8];
    const float* b_ih1 = (const float*)d_in[9];
    const float* b_hh1 = (const float*)d_in[10];
    const float* Wc_w  = (const float*)d_in[11];
    const float* Wc_b  = (const float*)d_in[12];
    float* out = (float*)d_out;

    float *x0, *h0a, *h0b, *xdec, *xp, *ys0, *ys1, *fin;
    cudaGetSymbolAddress((void**)&x0,   g_x0);
    cudaGetSymbolAddress((void**)&h0a,  g_h0a);
    cudaGetSymbolAddress((void**)&h0b,  g_h0b);
    cudaGetSymbolAddress((void**)&xdec, g_xdec);
    cudaGetSymbolAddress((void**)&xp,   g_xp);
    cudaGetSymbolAddress((void**)&ys0,  g_ys0);
    cudaGetSymbolAddress((void**)&ys1,  g_ys1);
    cudaGetSymbolAddress((void**)&fin,  g_final);

    cudaFuncSetAttribute(gemm_tf32<true>,  cudaFuncAttributeMaxDynamicSharedMemorySize, SMEM_COMP);
    cudaFuncSetAttribute(gemm_tf32<false>, cudaFuncAttributeMaxDynamicSharedMemorySize, SMEM_FAST);
    cudaFuncSetAttribute(gru_scan,         cudaFuncAttributeMaxDynamicSharedMemorySize, SMEM_SCAN);

    dim3 blk(256);

    // ---- h0 (fused small path) ----
    build_x0<<<BB, blk>>>(init, x0);
    gru_h0<<<128, blk>>>(W_ih0, b_ih0, b_hh0, x0, h0a);
    gru_h0<<<128, blk>>>(W_ih1, b_ih1, b_hh1, h0a, h0b);

    // ---- decoder inputs ----
    build_xdec<<<TT * BB, blk>>>(helper, emb, init, xdec);

    // ---- layer 0: xp (single-pass tf32) then persistent scan ----
    gemm_tf32<false><<<dim3(G3H / 128, TT * BB / 128), blk, SMEM_FAST>>>(
        xdec, W_ih0, xp, TT * BB, G3H, 2 * EE, b_ih0, 1);
    gru_scan<<<NCTA_SCAN, blk, SMEM_SCAN>>>(W_hh0, b_hh0, xp, h0a, ys0);

    // ---- layer 1: xp (single-pass tf32) then persistent scan ----
    gemm_tf32<false><<<dim3(G3H / 128, TT * BB / 128), blk, SMEM_FAST>>>(
        ys0, W_ih1, xp, TT * BB, G3H, HH, b_ih1, 1);
    gru_scan<<<NCTA_SCAN, blk, SMEM_SCAN>>>(W_hh1, b_hh1, xp, h0b, ys1);

    // ---- final = tanh(ys1 @ Wc_w^T + Wc_b), compensated ----
    gemm_tf32<true><<<dim3(EE / 128, TT * BB / 128), blk, SMEM_COMP>>>(
        ys1, Wc_w, fin, TT * BB, EE, HH, Wc_b, 1 | 2);

    // ---- logits = final @ emb^T, single-pass tf32, stored (B,T,V) ----
    gemm_tf32<false><<<dim3((VV + 127) / 128, TT * BB / 128), blk, SMEM_FAST>>>(
        fin, emb, out, TT * BB, VV, EE, nullptr, 4);
}

// round 10
// speedup vs baseline: 1.5674x; 1.0077x over previous
#include <cuda_runtime.h>
#include <cuda_bf16.h>
#include <math.h>
#include <stdint.h>

// Problem constants
#define BB 16      // batch
#define TT 64      // seq len
#define VV 50257   // vocab
#define EE 512     // embed
#define HH 1024    // hidden
#define G3H 3072   // 3*H

#define NCTA_SCAN 128   // persistent scan grid (<=148 SMs -> all resident)

// ---------------- scratch (no allocations allowed) ----------------
__device__ float g_x0[BB * 2 * EE];          // 16x1024
__device__ float g_h0a[BB * HH];             // layer0 h0
__device__ float g_h0b[BB * HH];             // layer1 h0
__device__ float g_xdec[TT * BB * 2 * EE];   // 1024x1024
__device__ float g_xp[TT * BB * G3H];        // 1024x3072 (reused for both layers)
__device__ float g_ys0[TT * BB * HH];        // 1024x1024
__device__ float g_ys1[TT * BB * HH];        // 1024x1024
__device__ float g_final[TT * BB * EE];      // 1024x512

// grid-barrier state (self-restoring: count returns to 0; gen compared by equality)
__device__ unsigned g_bar_count = 0;
__device__ unsigned g_bar_gen   = 0;

// ---------------- small builders ----------------
__global__ void build_x0(const float* __restrict__ init, float* __restrict__ x0) {
    int b = blockIdx.x;
    for (int c = threadIdx.x; c < EE; c += blockDim.x) {
        float v = init[b * EE + c];
        x0[b * (2 * EE) + c] = v;
        x0[b * (2 * EE) + EE + c] = v;
    }
}

__global__ void build_xdec(const int* __restrict__ helper,
                           const float* __restrict__ emb,
                           const float* __restrict__ init,
                           float* __restrict__ xdec) {
    int r = blockIdx.x;            // r = t*B + b
    int t = r >> 4;
    int b = r & 15;
    int tok = helper[b * TT + t];
    const float* src0 = emb + (size_t)tok * EE;
    const float* src1 = init + b * EE;
    float* dst = xdec + (size_t)r * (2 * EE);
    for (int c = threadIdx.x; c < EE; c += blockDim.x) {
        dst[c] = src0[c];
        dst[EE + c] = src1[c];
    }
}

// ---------------- tf32 helpers ----------------
__device__ __forceinline__ uint32_t f2tf32(float x) {
    uint32_t r;
    asm("cvt.rna.tf32.f32 %0, %1;" : "=r"(r) : "f"(x));
    return r;
}

__device__ __forceinline__ void mma_tf32(float* c, const uint32_t* a, const uint32_t* b) {
    asm volatile(
        "mma.sync.aligned.m16n8k8.row.col.f32.tf32.tf32.f32 "
        "{%0,%1,%2,%3}, {%4,%5,%6,%7}, {%8,%9}, {%0,%1,%2,%3};"
        : "+f"(c[0]), "+f"(c[1]), "+f"(c[2]), "+f"(c[3])
        : "r"(a[0]), "r"(a[1]), "r"(a[2]), "r"(a[3]), "r"(b[0]), "r"(b[1]));
}

// ---------------- tensor-core GEMM: C = A(MxK) * B(NxK)^T ----------------
// Block tile 128x128, K tile 32. 8 warps: warp (wm,wn) owns 64x32.
// Grid: blockIdx.x = M-tile (FAST axis), blockIdx.y = N-tile.
//   Concurrent CTAs span all M-tiles of one N-band -> each B tile is read
//   from DRAM once and served to the other M-CTAs from L2 (emb = 103 MB:
//   8x traffic reduction on the logits GEMM).
// Single-buffer + ks-XOR bank swizzle (STS conflict 4 -> 1).
// flags: bit0 = add bias[n]; bit1 = tanh; bit2 = (b,t) transposed store (logits)
// COMP: compensated tf32 split (Ah*Bh + Al*Bh + Ah*Bl) ~ fp32 accuracy.
template<bool COMP>
__global__ void __launch_bounds__(256)
gemm_tf32(const float* __restrict__ A, const float* __restrict__ B,
          float* __restrict__ C, int M, int N, int K,
          const float* __restrict__ bias, int flags) {
    extern __shared__ float smem[];
    float* Ah = smem;             // [ks=4][mt=8][ln=32][slot=4]  4096 floats
    float* Bh = smem + 4096;      // [ks=4][nt=16][ln=32][slot=2] 4096 floats
    float* Al = COMP ? (smem + 8192)  : nullptr;
    float* Bl = COMP ? (smem + 12288) : nullptr;

    const int tid  = threadIdx.x;
    const int lane = tid & 31;
    const int warp = tid >> 5;
    const int wm = warp >> 2;     // 0..1
    const int wn = warp & 3;      // 0..3
    const int m0 = blockIdx.x * 128;
    const int n0 = blockIdx.y * 128;

    float acc[4][4][4];
#pragma unroll
    for (int i = 0; i < 4; i++)
#pragma unroll
        for (int j = 0; j < 4; j++)
#pragma unroll
            for (int s = 0; s < 4; s++) acc[i][j][s] = 0.0f;

    const int lrow = tid >> 3;        // 0..31
    const int lk4  = (tid & 7) * 4;   // 0,4,...,28
    const int nK = K >> 5;

    float4 pa[4], pb[4];

    // ---- prefetch K-tile 0 ----
    {
        int kbase = lk4;
#pragma unroll
        for (int p = 0; p < 4; p++) {
            int gr = m0 + lrow + p * 32;
            pa[p] = (gr < M) ? *(const float4*)&A[(size_t)gr * K + kbase]
                             : make_float4(0.f, 0.f, 0.f, 0.f);
            int gn = n0 + lrow + p * 32;
            pb[p] = (gn < N) ? *(const float4*)&B[(size_t)gn * K + kbase]
                             : make_float4(0.f, 0.f, 0.f, 0.f);
        }
    }
    // store tile 0 into permuted smem (ks-XOR swizzled)
#pragma unroll
    for (int p = 0; p < 4; p++) {
        int m = lrow + p * 32;
        const float* av = (const float*)&pa[p];
        const float* bv = (const float*)&pb[p];
#pragma unroll
        for (int i = 0; i < 4; i++) {
            int k = lk4 + i;
            int ks = k >> 3, kc = k & 7;
            {
                int mt = m >> 4, r = m & 15;
                int ln = (((r & 7) << 2) | (kc & 3)) ^ ks;
                int slot = (r >> 3) | ((kc >> 2) << 1);
                int idx = (((ks * 8 + mt) * 32 + ln) << 2) | slot;
                float x = av[i];
                uint32_t hb = f2tf32(x);
                Ah[idx] = __uint_as_float(hb);
                if (COMP) Al[idx] = __uint_as_float(f2tf32(x - __uint_as_float(hb)));
            }
            {
                int nt = m >> 3;
                int ln = (((m & 7) << 2) | (kc & 3)) ^ ks;
                int slot = kc >> 2;
                int idx = (((ks * 16 + nt) * 32 + ln) << 1) | slot;
                float x = bv[i];
                uint32_t hb = f2tf32(x);
                Bh[idx] = __uint_as_float(hb);
                if (COMP) Bl[idx] = __uint_as_float(f2tf32(x - __uint_as_float(hb)));
            }
        }
    }
    __syncthreads();

    for (int kt = 0; kt < nK; kt++) {
        bool more = (kt + 1 < nK);
        if (more) {
            int kbase = (kt + 1) * 32 + lk4;
#pragma unroll
            for (int p = 0; p < 4; p++) {
                int gr = m0 + lrow + p * 32;
                pa[p] = (gr < M) ? *(const float4*)&A[(size_t)gr * K + kbase]
                                 : make_float4(0.f, 0.f, 0.f, 0.f);
                int gn = n0 + lrow + p * 32;
                pb[p] = (gn < N) ? *(const float4*)&B[(size_t)gn * K + kbase]
                                 : make_float4(0.f, 0.f, 0.f, 0.f);
            }
        }

        // ---- compute 4 k-steps (reads use lane^ks) ----
#pragma unroll
        for (int ks = 0; ks < 4; ks++) {
            const int lsw = lane ^ ks;
            uint32_t af[4][4], bf[4][2];
            uint32_t al[4][4], bl[4][2];
#pragma unroll
            for (int mt = 0; mt < 4; mt++) {
                const float4 v = *(const float4*)(Ah + (((ks * 8 + (wm * 4 + mt)) * 32 + lsw) << 2));
                af[mt][0] = __float_as_uint(v.x); af[mt][1] = __float_as_uint(v.y);
                af[mt][2] = __float_as_uint(v.z); af[mt][3] = __float_as_uint(v.w);
                if (COMP) {
                    const float4 w = *(const float4*)(Al + (((ks * 8 + (wm * 4 + mt)) * 32 + lsw) << 2));
                    al[mt][0] = __float_as_uint(w.x); al[mt][1] = __float_as_uint(w.y);
                    al[mt][2] = __float_as_uint(w.z); al[mt][3] = __float_as_uint(w.w);
                }
            }
#pragma unroll
            for (int nt = 0; nt < 4; nt++) {
                const float2 v = *(const float2*)(Bh + (((ks * 16 + (wn * 4 + nt)) * 32 + lsw) << 1));
                bf[nt][0] = __float_as_uint(v.x); bf[nt][1] = __float_as_uint(v.y);
                if (COMP) {
                    const float2 w = *(const float2*)(Bl + (((ks * 16 + (wn * 4 + nt)) * 32 + lsw) << 1));
                    bl[nt][0] = __float_as_uint(w.x); bl[nt][1] = __float_as_uint(w.y);
                }
            }
#pragma unroll
            for (int mt = 0; mt < 4; mt++)
#pragma unroll
                for (int nt = 0; nt < 4; nt++) {
                    mma_tf32(acc[mt][nt], af[mt], bf[nt]);
                    if (COMP) {
                        mma_tf32(acc[mt][nt], al[mt], bf[nt]);
                        mma_tf32(acc[mt][nt], af[mt], bl[nt]);
                    }
                }
        }
        __syncthreads();

        if (more) {
#pragma unroll
            for (int p = 0; p < 4; p++) {
                int m = lrow + p * 32;
                const float* av = (const float*)&pa[p];
                const float* bv = (const float*)&pb[p];
#pragma unroll
                for (int i = 0; i < 4; i++) {
                    int k = lk4 + i;
                    int ks = k >> 3, kc = k & 7;
                    {
                        int mt = m >> 4, r = m & 15;
                        int ln = (((r & 7) << 2) | (kc & 3)) ^ ks;
                        int slot = (r >> 3) | ((kc >> 2) << 1);
                        int idx = (((ks * 8 + mt) * 32 + ln) << 2) | slot;
                        float x = av[i];
                        uint32_t hb = f2tf32(x);
                        Ah[idx] = __uint_as_float(hb);
                        if (COMP) Al[idx] = __uint_as_float(f2tf32(x - __uint_as_float(hb)));
                    }
                    {
                        int nt = m >> 3;
                        int ln = (((m & 7) << 2) | (kc & 3)) ^ ks;
                        int slot = kc >> 2;
                        int idx = (((ks * 16 + nt) * 32 + ln) << 1) | slot;
                        float x = bv[i];
                        uint32_t hb = f2tf32(x);
                        Bh[idx] = __uint_as_float(hb);
                        if (COMP) Bl[idx] = __uint_as_float(f2tf32(x - __uint_as_float(hb)));
                    }
                }
            }
            __syncthreads();
        }
    }

    // ---- epilogue ----
    const int row = lane >> 2;          // 0..7
    const int col = (lane & 3) * 2;     // 0,2,4,6
#pragma unroll
    for (int mt = 0; mt < 4; mt++) {
#pragma unroll
        for (int nt = 0; nt < 4; nt++) {
#pragma unroll
            for (int s = 0; s < 4; s++) {
                int gm = m0 + wm * 64 + mt * 16 + row + ((s >> 1) ? 8 : 0);
                int gn = n0 + wn * 32 + nt * 8 + col + (s & 1);
                if (gm >= M || gn >= N) continue;
                float v = acc[mt][nt][s];
                if (flags & 1) v += bias[gn];
                if (flags & 2) v = tanhf(v);
                size_t idx;
                if (flags & 4) {
                    int b = gm & 15;     // gm = t*16 + b
                    int t = gm >> 4;
                    idx = (size_t)(b * TT + t) * (size_t)N + (size_t)gn;
                } else {
                    idx = (size_t)gm * (size_t)N + (size_t)gn;
                }
                C[idx] = v;
            }
        }
    }
}

// ---------------- fused h0 kernel (zero initial state) ----------------
__global__ __launch_bounds__(256)
void gru_h0(const float* __restrict__ Wih, const float* __restrict__ bih,
            const float* __restrict__ bhh,
            const float* __restrict__ x,      // BB x HH
            float* __restrict__ hout) {       // BB x HH
    const int warp = threadIdx.x >> 5;
    const int lane = threadIdx.x & 31;
    const int j = blockIdx.x * 8 + warp;

    float accr[BB], accz[BB], accn[BB];
#pragma unroll
    for (int b = 0; b < BB; b++) { accr[b] = 0.f; accz[b] = 0.f; accn[b] = 0.f; }

    const float4* wr = (const float4*)(Wih + (size_t)j * HH);
    const float4* wz = (const float4*)(Wih + (size_t)(HH + j) * HH);
    const float4* wn = (const float4*)(Wih + (size_t)(2 * HH + j) * HH);
    const float4* x4 = (const float4*)x;

#pragma unroll
    for (int it = 0; it < 8; it++) {
        int k4 = it * 32 + lane;
        float4 a = wr[k4];
        float4 bq = wz[k4];
        float4 c = wn[k4];
#pragma unroll
        for (int b = 0; b < BB; b++) {
            float4 hv = x4[b * 256 + k4];
            accr[b] = fmaf(a.x, hv.x, fmaf(a.y, hv.y, fmaf(a.z, hv.z, fmaf(a.w, hv.w, accr[b]))));
            accz[b] = fmaf(bq.x, hv.x, fmaf(bq.y, hv.y, fmaf(bq.z, hv.z, fmaf(bq.w, hv.w, accz[b]))));
            accn[b] = fmaf(c.x, hv.x, fmaf(c.y, hv.y, fmaf(c.z, hv.z, fmaf(c.w, hv.w, accn[b]))));
        }
    }

    float sr = 0.f, sz = 0.f, sn = 0.f;
#pragma unroll
    for (int b = 0; b < BB; b++) {
        float r = accr[b], z = accz[b], n = accn[b];
#pragma unroll
        for (int off = 16; off > 0; off >>= 1) {
            r += __shfl_xor_sync(0xFFFFFFFFu, r, off);
            z += __shfl_xor_sync(0xFFFFFFFFu, z, off);
            n += __shfl_xor_sync(0xFFFFFFFFu, n, off);
        }
        if (lane == b) { sr = r; sz = z; sn = n; }
    }

    if (lane < BB) {
        float xr = sr + bih[j];
        float xz = sz + bih[HH + j];
        float xn = sn + bih[2 * HH + j];
        float r = 1.f / (1.f + expf(-(xr + bhh[j])));
        float z = 1.f / (1.f + expf(-(xz + bhh[HH + j])));
        float n = tanhf(xn + r * bhh[2 * HH + j]);
        hout[lane * HH + j] = (1.f - z) * n;
    }
}

// ---------------- persistent GRU scan (one layer, all 64 steps) ----------------
__device__ __forceinline__ void grid_barrier() {
    __syncthreads();
    if (threadIdx.x == 0) {
        __threadfence();
        unsigned gen = atomicAdd(&g_bar_gen, 0u);     // read gen BEFORE arriving
        unsigned arrived = atomicAdd(&g_bar_count, 1u);
        if (arrived == NCTA_SCAN - 1) {
            g_bar_count = 0;
            __threadfence();
            atomicAdd(&g_bar_gen, 1u);
        } else {
            while (atomicAdd(&g_bar_gen, 0u) == gen) { __nanosleep(32); }
        }
    }
    __syncthreads();
}

__global__ void __launch_bounds__(256)
gru_scan(const float* __restrict__ Whh, const float* __restrict__ bhh,
         const float* __restrict__ xp,    // TT x BB x 3H (includes b_ih)
         const float* __restrict__ h0,    // BB x HH
         float* __restrict__ ys) {        // TT x BB x HH
    extern __shared__ float hs[];         // BB*HH floats = 64 KB
    const int tid  = threadIdx.x;
    const int warp = tid >> 5;
    const int lane = tid & 31;
    const int j = blockIdx.x * 8 + warp;  // hidden unit

    const float4* wr = (const float4*)(Whh + (size_t)j * HH);
    const float4* wz = (const float4*)(Whh + (size_t)(HH + j) * HH);
    const float4* wn = (const float4*)(Whh + (size_t)(2 * HH + j) * HH);
    float4 wcr[8], wcz[8], wcn[8];
#pragma unroll
    for (int it = 0; it < 8; it++) {
        int k4 = it * 32 + lane;
        wcr[it] = wr[k4];
        wcz[it] = wz[k4];
        wcn[it] = wn[k4];
    }
    const float bhr = bhh[j];
    const float bhz = bhh[HH + j];
    const float bhn = bhh[2 * HH + j];

    for (int t = 0; t < TT; t++) {
        const float4* hp4 = (const float4*)((t == 0) ? h0 : (ys + (size_t)(t - 1) * BB * HH));
#pragma unroll 4
        for (int idx = tid; idx < BB * HH / 4; idx += 256)
            ((float4*)hs)[idx] = hp4[idx];
        __syncthreads();

        float accr[BB], accz[BB], accn[BB];
#pragma unroll
        for (int b = 0; b < BB; b++) { accr[b] = 0.f; accz[b] = 0.f; accn[b] = 0.f; }

        const float4* h4 = (const float4*)hs;
#pragma unroll
        for (int it = 0; it < 8; it++) {
            int k4 = it * 32 + lane;
            float4 a = wcr[it], bq = wcz[it], c = wcn[it];
#pragma unroll
            for (int b = 0; b < BB; b++) {
                float4 hv = h4[b * 256 + k4];
                accr[b] = fmaf(a.x, hv.x, fmaf(a.y, hv.y, fmaf(a.z, hv.z, fmaf(a.w, hv.w, accr[b]))));
                accz[b] = fmaf(bq.x, hv.x, fmaf(bq.y, hv.y, fmaf(bq.z, hv.z, fmaf(bq.w, hv.w, accz[b]))));
                accn[b] = fmaf(c.x, hv.x, fmaf(c.y, hv.y, fmaf(c.z, hv.z, fmaf(c.w, hv.w, accn[b]))));
            }
        }

        float sr = 0.f, sz = 0.f, sn = 0.f;
#pragma unroll
        for (int b = 0; b < BB; b++) {
            float r = accr[b], z = accz[b], n = accn[b];
#pragma unroll
            for (int off = 16; off > 0; off >>= 1) {
                r += __shfl_xor_sync(0xFFFFFFFFu, r, off);
                z += __shfl_xor_sync(0xFFFFFFFFu, z, off);
                n += __shfl_xor_sync(0xFFFFFFFFu, n, off);
            }
            if (lane == b) { sr = r; sz = z; sn = n; }
        }

        if (lane < BB) {
            int b = lane;
            const float* xg = xp + (size_t)t * BB * G3H + (size_t)b * G3H;
            float xr = xg[j];
            float xz = xg[HH + j];
            float xn = xg[2 * HH + j];
            float hp = hs[b * HH + j];
            float r = 1.f / (1.f + expf(-(xr + sr + bhr)));
            float z = 1.f / (1.f + expf(-(xz + sz + bhz)));
            float n = tanhf(xn + r * (sn + bhn));
            ys[(size_t)t * BB * HH + b * HH + j] = (1.f - z) * n + z * hp;
        }

        grid_barrier();   // all writes of step t visible before step t+1 staging
    }
}

// ---------------- host orchestration ----------------
#define SMEM_COMP  (16384 * 4)   // 64 KB
#define SMEM_FAST  (16384 * 2)   // 32 KB
#define SMEM_SCAN  (BB * HH * 4) // 64 KB

extern "C" void kernel_launch(void* const* d_in, const int* in_sizes, int n_in,
                              void* d_out, int out_size) {
    const float* init  = (const float*)d_in[0];
    const int*   helper= (const int*)  d_in[1];
    const float* emb   = (const float*)d_in[2];
    const float* W_ih0 = (const float*)d_in[3];
    const float* W_hh0 = (const float*)d_in[4];
    const float* b_ih0 = (const float*)d_in[5];
    const float* b_hh0 = (const float*)d_in[6];
    const float* W_ih1 = (const float*)d_in[7];
    const float* W_hh1 = (const float*)d_in[8];
    const float* b_ih1 = (const float*)d_in[9];
    const float* b_hh1 = (const float*)d_in[10];
    const float* Wc_w  = (const float*)d_in[11];
    const float* Wc_b  = (const float*)d_in[12];
    float* out = (float*)d_out;

    float *x0, *h0a, *h0b, *xdec, *xp, *ys0, *ys1, *fin;
    cudaGetSymbolAddress((void**)&x0,   g_x0);
    cudaGetSymbolAddress((void**)&h0a,  g_h0a);
    cudaGetSymbolAddress((void**)&h0b,  g_h0b);
    cudaGetSymbolAddress((void**)&xdec, g_xdec);
    cudaGetSymbolAddress((void**)&xp,   g_xp);
    cudaGetSymbolAddress((void**)&ys0,  g_ys0);
    cudaGetSymbolAddress((void**)&ys1,  g_ys1);
    cudaGetSymbolAddress((void**)&fin,  g_final);

    cudaFuncSetAttribute(gemm_tf32<true>,  cudaFuncAttributeMaxDynamicSharedMemorySize, SMEM_COMP);
    cudaFuncSetAttribute(gemm_tf32<false>, cudaFuncAttributeMaxDynamicSharedMemorySize, SMEM_FAST);
    cudaFuncSetAttribute(gru_scan,         cudaFuncAttributeMaxDynamicSharedMemorySize, SMEM_SCAN);

    dim3 blk(256);

    // ---- h0 (fused small path) ----
    build_x0<<<BB, blk>>>(init, x0);
    gru_h0<<<128, blk>>>(W_ih0, b_ih0, b_hh0, x0, h0a);
    gru_h0<<<128, blk>>>(W_ih1, b_ih1, b_hh1, h0a, h0b);

    // ---- decoder inputs ----
    build_xdec<<<TT * BB, blk>>>(helper, emb, init, xdec);

    // ---- layer 0: xp (single-pass tf32) then persistent scan ----
    // grid: x = M-tiles (fast), y = N-tiles -> B tiles L2-shared across M-CTAs
    gemm_tf32<false><<<dim3(TT * BB / 128, G3H / 128), blk, SMEM_FAST>>>(
        xdec, W_ih0, xp, TT * BB, G3H, 2 * EE, b_ih0, 1);
    gru_scan<<<NCTA_SCAN, blk, SMEM_SCAN>>>(W_hh0, b_hh0, xp, h0a, ys0);

    // ---- layer 1: xp (single-pass tf32) then persistent scan ----
    gemm_tf32<false><<<dim3(TT * BB / 128, G3H / 128), blk, SMEM_FAST>>>(
        ys0, W_ih1, xp, TT * BB, G3H, HH, b_ih1, 1);
    gru_scan<<<NCTA_SCAN, blk, SMEM_SCAN>>>(W_hh1, b_hh1, xp, h0b, ys1);

    // ---- final = tanh(ys1 @ Wc_w^T + Wc_b), compensated ----
    gemm_tf32<true><<<dim3(TT * BB / 128, EE / 128), blk, SMEM_COMP>>>(
        ys1, Wc_w, fin, TT * BB, EE, HH, Wc_b, 1 | 2);

    // ---- logits = final @ emb^T, single-pass tf32, stored (B,T,V) ----
    gemm_tf32<false><<<dim3(TT * BB / 128, (VV + 127) / 128), blk, SMEM_FAST>>>(
        fin, emb, out, TT * BB, VV, EE, nullptr, 4);
}

// round 11
// speedup vs baseline: 1.6042x; 1.0235x over previous
#include <cuda_runtime.h>
#include <cuda_bf16.h>
#include <math.h>
#include <stdint.h>

// Problem constants
#define BB 16      // batch
#define TT 64      // seq len
#define VV 50257   // vocab
#define EE 512     // embed
#define HH 1024    // hidden
#define G3H 3072   // 3*H

#define NCTA_SCAN 128   // persistent scan grid (<=148 SMs -> all resident)

// ---------------- scratch (no allocations allowed) ----------------
__device__ float g_x0[BB * 2 * EE];          // 16x1024
__device__ float g_h0a[BB * HH];             // layer0 h0
__device__ float g_h0b[BB * HH];             // layer1 h0
__device__ float g_xdec[TT * BB * 2 * EE];   // 1024x1024
__device__ float g_xp[TT * BB * G3H];        // 1024x3072 (reused for both layers)
__device__ float g_ys0[TT * BB * HH];        // 1024x1024
__device__ float g_ys1[TT * BB * HH];        // 1024x1024
__device__ float g_final[TT * BB * EE];      // 1024x512

// grid-barrier state (self-restoring: count returns to 0; gen compared by equality)
__device__ unsigned g_bar_count = 0;
__device__ unsigned g_bar_gen   = 0;

// ---------------- small builders ----------------
__global__ void build_x0(const float* __restrict__ init, float* __restrict__ x0) {
    int b = blockIdx.x;
    for (int c = threadIdx.x; c < EE; c += blockDim.x) {
        float v = init[b * EE + c];
        x0[b * (2 * EE) + c] = v;
        x0[b * (2 * EE) + EE + c] = v;
    }
}

__global__ void build_xdec(const int* __restrict__ helper,
                           const float* __restrict__ emb,
                           const float* __restrict__ init,
                           float* __restrict__ xdec) {
    int r = blockIdx.x;            // r = t*B + b
    int t = r >> 4;
    int b = r & 15;
    int tok = helper[b * TT + t];
    const float* src0 = emb + (size_t)tok * EE;
    const float* src1 = init + b * EE;
    float* dst = xdec + (size_t)r * (2 * EE);
    for (int c = threadIdx.x; c < EE; c += blockDim.x) {
        dst[c] = src0[c];
        dst[EE + c] = src1[c];
    }
}

// ---------------- tf32 helpers ----------------
__device__ __forceinline__ uint32_t f2tf32(float x) {
    uint32_t r;
    asm("cvt.rna.tf32.f32 %0, %1;" : "=r"(r) : "f"(x));
    return r;
}

__device__ __forceinline__ void mma_tf32(float* c, const uint32_t* a, const uint32_t* b) {
    asm volatile(
        "mma.sync.aligned.m16n8k8.row.col.f32.tf32.tf32.f32 "
        "{%0,%1,%2,%3}, {%4,%5,%6,%7}, {%8,%9}, {%0,%1,%2,%3};"
        : "+f"(c[0]), "+f"(c[1]), "+f"(c[2]), "+f"(c[3])
        : "r"(a[0]), "r"(a[1]), "r"(a[2]), "r"(a[3]), "r"(b[0]), "r"(b[1]));
}

// ---------------- tensor-core GEMM: C = A(MxK) * B(NxK)^T ----------------
// Block tile 128x128, K tile 32. 8 warps: warp (wm,wn) owns 64x32.
// Grid: blockIdx.x = M-tile (FAST axis), blockIdx.y = N-tile (B-tile L2 reuse).
// DOUBLE-BUFFERED with COMPILE-TIME stage offsets (kt-loop unrolled by 2):
//   one __syncthreads per K-tile; STS of tile k+1 overlaps MMA drain of tile k.
//   Stage addresses are smem+constexpr -> immediate LDS/STS (round-7 lesson:
//   dynamic stage pointers destroy codegen).
// ks-XOR bank swizzle on fragment rows (STS conflict 4 -> 1).
// flags: bit0 = add bias[n]; bit1 = tanh; bit2 = (b,t) transposed store (logits)
// COMP: compensated tf32 split (Ah*Bh + Al*Bh + Ah*Bl) ~ fp32 accuracy.

#define STG_FAST 8192    // floats per stage: Ah(4096)+Bh(4096)
#define STG_COMP 16384   // + Al(4096)+Bl(4096)

template<bool COMP>
__device__ __forceinline__ void load_tile(
    const float* __restrict__ A, const float* __restrict__ B,
    int M, int N, int K, int m0, int n0, int kbase, int lrow,
    float4* pa, float4* pb) {
#pragma unroll
    for (int p = 0; p < 4; p++) {
        int gr = m0 + lrow + p * 32;
        pa[p] = (gr < M) ? *(const float4*)&A[(size_t)gr * K + kbase]
                         : make_float4(0.f, 0.f, 0.f, 0.f);
        int gn = n0 + lrow + p * 32;
        pb[p] = (gn < N) ? *(const float4*)&B[(size_t)gn * K + kbase]
                         : make_float4(0.f, 0.f, 0.f, 0.f);
    }
}

template<bool COMP>
__device__ __forceinline__ void store_stage(
    float* stage, const float4* pa, const float4* pb, int lrow, int lk4) {
    float* Ah = stage;
    float* Bh = stage + 4096;
    float* Al = COMP ? (stage + 8192)  : nullptr;
    float* Bl = COMP ? (stage + 12288) : nullptr;
#pragma unroll
    for (int p = 0; p < 4; p++) {
        int m = lrow + p * 32;
        const float* av = (const float*)&pa[p];
        const float* bv = (const float*)&pb[p];
#pragma unroll
        for (int i = 0; i < 4; i++) {
            int k = lk4 + i;
            int ks = k >> 3, kc = k & 7;
            {
                int mt = m >> 4, r = m & 15;
                int ln = (((r & 7) << 2) | (kc & 3)) ^ ks;
                int slot = (r >> 3) | ((kc >> 2) << 1);
                int idx = (((ks * 8 + mt) * 32 + ln) << 2) | slot;
                float x = av[i];
                uint32_t hb = f2tf32(x);
                Ah[idx] = __uint_as_float(hb);
                if (COMP) Al[idx] = __uint_as_float(f2tf32(x - __uint_as_float(hb)));
            }
            {
                int nt = m >> 3;
                int ln = (((m & 7) << 2) | (kc & 3)) ^ ks;
                int slot = kc >> 2;
                int idx = (((ks * 16 + nt) * 32 + ln) << 1) | slot;
                float x = bv[i];
                uint32_t hb = f2tf32(x);
                Bh[idx] = __uint_as_float(hb);
                if (COMP) Bl[idx] = __uint_as_float(f2tf32(x - __uint_as_float(hb)));
            }
        }
    }
}

template<bool COMP>
__device__ __forceinline__ void compute_stage(
    const float* stage, float acc[4][4][4], int wm, int wn, int lane) {
    const float* Ah = stage;
    const float* Bh = stage + 4096;
    const float* Al = COMP ? (stage + 8192)  : nullptr;
    const float* Bl = COMP ? (stage + 12288) : nullptr;
#pragma unroll
    for (int ks = 0; ks < 4; ks++) {
        const int lsw = lane ^ ks;
        uint32_t af[4][4], bf[4][2];
        uint32_t al[4][4], bl[4][2];
#pragma unroll
        for (int mt = 0; mt < 4; mt++) {
            const float4 v = *(const float4*)(Ah + (((ks * 8 + (wm * 4 + mt)) * 32 + lsw) << 2));
            af[mt][0] = __float_as_uint(v.x); af[mt][1] = __float_as_uint(v.y);
            af[mt][2] = __float_as_uint(v.z); af[mt][3] = __float_as_uint(v.w);
            if (COMP) {
                const float4 w = *(const float4*)(Al + (((ks * 8 + (wm * 4 + mt)) * 32 + lsw) << 2));
                al[mt][0] = __float_as_uint(w.x); al[mt][1] = __float_as_uint(w.y);
                al[mt][2] = __float_as_uint(w.z); al[mt][3] = __float_as_uint(w.w);
            }
        }
#pragma unroll
        for (int nt = 0; nt < 4; nt++) {
            const float2 v = *(const float2*)(Bh + (((ks * 16 + (wn * 4 + nt)) * 32 + lsw) << 1));
            bf[nt][0] = __float_as_uint(v.x); bf[nt][1] = __float_as_uint(v.y);
            if (COMP) {
                const float2 w = *(const float2*)(Bl + (((ks * 16 + (wn * 4 + nt)) * 32 + lsw) << 1));
                bl[nt][0] = __float_as_uint(w.x); bl[nt][1] = __float_as_uint(w.y);
            }
        }
#pragma unroll
        for (int mt = 0; mt < 4; mt++)
#pragma unroll
            for (int nt = 0; nt < 4; nt++) {
                mma_tf32(acc[mt][nt], af[mt], bf[nt]);
                if (COMP) {
                    mma_tf32(acc[mt][nt], al[mt], bf[nt]);
                    mma_tf32(acc[mt][nt], af[mt], bl[nt]);
                }
            }
    }
}

template<bool COMP>
__global__ void __launch_bounds__(256)
gemm_tf32(const float* __restrict__ A, const float* __restrict__ B,
          float* __restrict__ C, int M, int N, int K,
          const float* __restrict__ bias, int flags) {
    extern __shared__ float smem[];
    constexpr int STG = COMP ? STG_COMP : STG_FAST;
    float* const s0 = smem;          // compile-time offsets from dynamic base
    float* const s1 = smem + STG;

    const int tid  = threadIdx.x;
    const int lane = tid & 31;
    const int warp = tid >> 5;
    const int wm = warp >> 2;     // 0..1
    const int wn = warp & 3;      // 0..3
    const int m0 = blockIdx.x * 128;
    const int n0 = blockIdx.y * 128;

    float acc[4][4][4];
#pragma unroll
    for (int i = 0; i < 4; i++)
#pragma unroll
        for (int j = 0; j < 4; j++)
#pragma unroll
            for (int s = 0; s < 4; s++) acc[i][j][s] = 0.0f;

    const int lrow = tid >> 3;        // 0..31
    const int lk4  = (tid & 7) * 4;   // 0,4,...,28
    const int nK = K >> 5;            // all call sites: nK even (16 or 32)

    float4 pa[4], pb[4];

    // ---- prologue: tile 0 -> stage 0 ----
    load_tile<COMP>(A, B, M, N, K, m0, n0, lk4, lrow, pa, pb);
    store_stage<COMP>(s0, pa, pb, lrow, lk4);
    __syncthreads();

    for (int kt = 0; kt < nK; kt += 2) {
        // -- even tile: compute s0, fill s1 --
        if (kt + 1 < nK)
            load_tile<COMP>(A, B, M, N, K, m0, n0, (kt + 1) * 32 + lk4, lrow, pa, pb);
        compute_stage<COMP>(s0, acc, wm, wn, lane);
        if (kt + 1 < nK) {
            store_stage<COMP>(s1, pa, pb, lrow, lk4);
            __syncthreads();    // s1 ready; everyone done reading s0

            // -- odd tile: compute s1, fill s0 --
            if (kt + 2 < nK)
                load_tile<COMP>(A, B, M, N, K, m0, n0, (kt + 2) * 32 + lk4, lrow, pa, pb);
            compute_stage<COMP>(s1, acc, wm, wn, lane);
            if (kt + 2 < nK) {
                store_stage<COMP>(s0, pa, pb, lrow, lk4);
                __syncthreads();  // s0 ready; everyone done reading s1
            }
        }
    }

    // ---- epilogue ----
    const int row = lane >> 2;          // 0..7
    const int col = (lane & 3) * 2;     // 0,2,4,6
#pragma unroll
    for (int mt = 0; mt < 4; mt++) {
#pragma unroll
        for (int nt = 0; nt < 4; nt++) {
#pragma unroll
            for (int s = 0; s < 4; s++) {
                int gm = m0 + wm * 64 + mt * 16 + row + ((s >> 1) ? 8 : 0);
                int gn = n0 + wn * 32 + nt * 8 + col + (s & 1);
                if (gm >= M || gn >= N) continue;
                float v = acc[mt][nt][s];
                if (flags & 1) v += bias[gn];
                if (flags & 2) v = tanhf(v);
                size_t idx;
                if (flags & 4) {
                    int b = gm & 15;     // gm = t*16 + b
                    int t = gm >> 4;
                    idx = (size_t)(b * TT + t) * (size_t)N + (size_t)gn;
                } else {
                    idx = (size_t)gm * (size_t)N + (size_t)gn;
                }
                C[idx] = v;
            }
        }
    }
}

// ---------------- fused h0 kernel (zero initial state) ----------------
__global__ __launch_bounds__(256)
void gru_h0(const float* __restrict__ Wih, const float* __restrict__ bih,
            const float* __restrict__ bhh,
            const float* __restrict__ x,      // BB x HH
            float* __restrict__ hout) {       // BB x HH
    const int warp = threadIdx.x >> 5;
    const int lane = threadIdx.x & 31;
    const int j = blockIdx.x * 8 + warp;

    float accr[BB], accz[BB], accn[BB];
#pragma unroll
    for (int b = 0; b < BB; b++) { accr[b] = 0.f; accz[b] = 0.f; accn[b] = 0.f; }

    const float4* wr = (const float4*)(Wih + (size_t)j * HH);
    const float4* wz = (const float4*)(Wih + (size_t)(HH + j) * HH);
    const float4* wn = (const float4*)(Wih + (size_t)(2 * HH + j) * HH);
    const float4* x4 = (const float4*)x;

#pragma unroll
    for (int it = 0; it < 8; it++) {
        int k4 = it * 32 + lane;
        float4 a = wr[k4];
        float4 bq = wz[k4];
        float4 c = wn[k4];
#pragma unroll
        for (int b = 0; b < BB; b++) {
            float4 hv = x4[b * 256 + k4];
            accr[b] = fmaf(a.x, hv.x, fmaf(a.y, hv.y, fmaf(a.z, hv.z, fmaf(a.w, hv.w, accr[b]))));
            accz[b] = fmaf(bq.x, hv.x, fmaf(bq.y, hv.y, fmaf(bq.z, hv.z, fmaf(bq.w, hv.w, accz[b]))));
            accn[b] = fmaf(c.x, hv.x, fmaf(c.y, hv.y, fmaf(c.z, hv.z, fmaf(c.w, hv.w, accn[b]))));
        }
    }

    float sr = 0.f, sz = 0.f, sn = 0.f;
#pragma unroll
    for (int b = 0; b < BB; b++) {
        float r = accr[b], z = accz[b], n = accn[b];
#pragma unroll
        for (int off = 16; off > 0; off >>= 1) {
            r += __shfl_xor_sync(0xFFFFFFFFu, r, off);
            z += __shfl_xor_sync(0xFFFFFFFFu, z, off);
            n += __shfl_xor_sync(0xFFFFFFFFu, n, off);
        }
        if (lane == b) { sr = r; sz = z; sn = n; }
    }

    if (lane < BB) {
        float xr = sr + bih[j];
        float xz = sz + bih[HH + j];
        float xn = sn + bih[2 * HH + j];
        float r = 1.f / (1.f + expf(-(xr + bhh[j])));
        float z = 1.f / (1.f + expf(-(xz + bhh[HH + j])));
        float n = tanhf(xn + r * bhh[2 * HH + j]);
        hout[lane * HH + j] = (1.f - z) * n;
    }
}

// ---------------- persistent GRU scan (one layer, all 64 steps) ----------------
__device__ __forceinline__ void grid_barrier() {
    __syncthreads();
    if (threadIdx.x == 0) {
        __threadfence();
        unsigned gen = atomicAdd(&g_bar_gen, 0u);     // read gen BEFORE arriving
        unsigned arrived = atomicAdd(&g_bar_count, 1u);
        if (arrived == NCTA_SCAN - 1) {
            g_bar_count = 0;
            __threadfence();
            atomicAdd(&g_bar_gen, 1u);
        } else {
            while (atomicAdd(&g_bar_gen, 0u) == gen) { __nanosleep(32); }
        }
    }
    __syncthreads();
}

__global__ void __launch_bounds__(256)
gru_scan(const float* __restrict__ Whh, const float* __restrict__ bhh,
         const float* __restrict__ xp,    // TT x BB x 3H (includes b_ih)
         const float* __restrict__ h0,    // BB x HH
         float* __restrict__ ys) {        // TT x BB x HH
    extern __shared__ float hs[];         // BB*HH floats = 64 KB
    const int tid  = threadIdx.x;
    const int warp = tid >> 5;
    const int lane = tid & 31;
    const int j = blockIdx.x * 8 + warp;  // hidden unit

    const float4* wr = (const float4*)(Whh + (size_t)j * HH);
    const float4* wz = (const float4*)(Whh + (size_t)(HH + j) * HH);
    const float4* wn = (const float4*)(Whh + (size_t)(2 * HH + j) * HH);
    float4 wcr[8], wcz[8], wcn[8];
#pragma unroll
    for (int it = 0; it < 8; it++) {
        int k4 = it * 32 + lane;
        wcr[it] = wr[k4];
        wcz[it] = wz[k4];
        wcn[it] = wn[k4];
    }
    const float bhr = bhh[j];
    const float bhz = bhh[HH + j];
    const float bhn = bhh[2 * HH + j];

    for (int t = 0; t < TT; t++) {
        const float4* hp4 = (const float4*)((t == 0) ? h0 : (ys + (size_t)(t - 1) * BB * HH));
#pragma unroll 4
        for (int idx = tid; idx < BB * HH / 4; idx += 256)
            ((float4*)hs)[idx] = hp4[idx];
        __syncthreads();

        float accr[BB], accz[BB], accn[BB];
#pragma unroll
        for (int b = 0; b < BB; b++) { accr[b] = 0.f; accz[b] = 0.f; accn[b] = 0.f; }

        const float4* h4 = (const float4*)hs;
#pragma unroll
        for (int it = 0; it < 8; it++) {
            int k4 = it * 32 + lane;
            float4 a = wcr[it], bq = wcz[it], c = wcn[it];
#pragma unroll
            for (int b = 0; b < BB; b++) {
                float4 hv = h4[b * 256 + k4];
                accr[b] = fmaf(a.x, hv.x, fmaf(a.y, hv.y, fmaf(a.z, hv.z, fmaf(a.w, hv.w, accr[b]))));
                accz[b] = fmaf(bq.x, hv.x, fmaf(bq.y, hv.y, fmaf(bq.z, hv.z, fmaf(bq.w, hv.w, accz[b]))));
                accn[b] = fmaf(c.x, hv.x, fmaf(c.y, hv.y, fmaf(c.z, hv.z, fmaf(c.w, hv.w, accn[b]))));
            }
        }

        float sr = 0.f, sz = 0.f, sn = 0.f;
#pragma unroll
        for (int b = 0; b < BB; b++) {
            float r = accr[b], z = accz[b], n = accn[b];
#pragma unroll
            for (int off = 16; off > 0; off >>= 1) {
                r += __shfl_xor_sync(0xFFFFFFFFu, r, off);
                z += __shfl_xor_sync(0xFFFFFFFFu, z, off);
                n += __shfl_xor_sync(0xFFFFFFFFu, n, off);
            }
            if (lane == b) { sr = r; sz = z; sn = n; }
        }

        if (lane < BB) {
            int b = lane;
            const float* xg = xp + (size_t)t * BB * G3H + (size_t)b * G3H;
            float xr = xg[j];
            float xz = xg[HH + j];
            float xn = xg[2 * HH + j];
            float hp = hs[b * HH + j];
            float r = 1.f / (1.f + expf(-(xr + sr + bhr)));
            float z = 1.f / (1.f + expf(-(xz + sz + bhz)));
            float n = tanhf(xn + r * (sn + bhn));
            ys[(size_t)t * BB * HH + b * HH + j] = (1.f - z) * n + z * hp;
        }

        grid_barrier();   // all writes of step t visible before step t+1 staging
    }
}

// ---------------- host orchestration ----------------
#define SMEM_COMP  (2 * STG_COMP * 4)   // 128 KB
#define SMEM_FAST  (2 * STG_FAST * 4)   // 64 KB
#define SMEM_SCAN  (BB * HH * 4)        // 64 KB

extern "C" void kernel_launch(void* const* d_in, const int* in_sizes, int n_in,
                              void* d_out, int out_size) {
    const float* init  = (const float*)d_in[0];
    const int*   helper= (const int*)  d_in[1];
    const float* emb   = (const float*)d_in[2];
    const float* W_ih0 = (const float*)d_in[3];
    const float* W_hh0 = (const float*)d_in[4];
    const float* b_ih0 = (const float*)d_in[5];
    const float* b_hh0 = (const float*)d_in[6];
    const float* W_ih1 = (const float*)d_in[7];
    const float* W_hh1 = (const float*)d_in[8];
    const float* b_ih1 = (const float*)d_in[9];
    const float* b_hh1 = (const float*)d_in[10];
    const float* Wc_w  = (const float*)d_in[11];
    const float* Wc_b  = (const float*)d_in[12];
    float* out = (float*)d_out;

    float *x0, *h0a, *h0b, *xdec, *xp, *ys0, *ys1, *fin;
    cudaGetSymbolAddress((void**)&x0,   g_x0);
    cudaGetSymbolAddress((void**)&h0a,  g_h0a);
    cudaGetSymbolAddress((void**)&h0b,  g_h0b);
    cudaGetSymbolAddress((void**)&xdec, g_xdec);
    cudaGetSymbolAddress((void**)&xp,   g_xp);
    cudaGetSymbolAddress((void**)&ys0,  g_ys0);
    cudaGetSymbolAddress((void**)&ys1,  g_ys1);
    cudaGetSymbolAddress((void**)&fin,  g_final);

    cudaFuncSetAttribute(gemm_tf32<true>,  cudaFuncAttributeMaxDynamicSharedMemorySize, SMEM_COMP);
    cudaFuncSetAttribute(gemm_tf32<false>, cudaFuncAttributeMaxDynamicSharedMemorySize, SMEM_FAST);
    cudaFuncSetAttribute(gru_scan,         cudaFuncAttributeMaxDynamicSharedMemorySize, SMEM_SCAN);

    dim3 blk(256);

    // ---- h0 (fused small path) ----
    build_x0<<<BB, blk>>>(init, x0);
    gru_h0<<<128, blk>>>(W_ih0, b_ih0, b_hh0, x0, h0a);
    gru_h0<<<128, blk>>>(W_ih1, b_ih1, b_hh1, h0a, h0b);

    // ---- decoder inputs ----
    build_xdec<<<TT * BB, blk>>>(helper, emb, init, xdec);

    // ---- layer 0: xp (single-pass tf32) then persistent scan ----
    gemm_tf32<false><<<dim3(TT * BB / 128, G3H / 128), blk, SMEM_FAST>>>(
        xdec, W_ih0, xp, TT * BB, G3H, 2 * EE, b_ih0, 1);
    gru_scan<<<NCTA_SCAN, blk, SMEM_SCAN>>>(W_hh0, b_hh0, xp, h0a, ys0);

    // ---- layer 1: xp (single-pass tf32) then persistent scan ----
    gemm_tf32<false><<<dim3(TT * BB / 128, G3H / 128), blk, SMEM_FAST>>>(
        ys0, W_ih1, xp, TT * BB, G3H, HH, b_ih1, 1);
    gru_scan<<<NCTA_SCAN, blk, SMEM_SCAN>>>(W_hh1, b_hh1, xp, h0b, ys1);

    // ---- final = tanh(ys1 @ Wc_w^T + Wc_b), compensated ----
    gemm_tf32<true><<<dim3(TT * BB / 128, EE / 128), blk, SMEM_COMP>>>(
        ys1, Wc_w, fin, TT * BB, EE, HH, Wc_b, 1 | 2);

    // ---- logits = final @ emb^T, single-pass tf32, stored (B,T,V) ----
    gemm_tf32<false><<<dim3(TT * BB / 128, (VV + 127) / 128), blk, SMEM_FAST>>>(
        fin, emb, out, TT * BB, VV, EE, nullptr, 4);
}